// round 11
// baseline (speedup 1.0000x reference)
#include <cuda_runtime.h>
#include <cstdint>
#include <cstddef>

#define N_TOK 32768
#define DIM   512
#define NCODE 4096
#define NQ    4

typedef unsigned long long ull;

// ---------------- device-global scratch (no allocations allowed) ----------------
__device__ float  g_residual[N_TOK * DIM];   // 64 MB
__device__ float  g_rnorm[N_TOK];            // per-token ||r||^2 (fp32), per stage
__device__ float  g_pv[2 * N_TOK];           // per-half best value
__device__ int    g_pi[2 * N_TOK];           // per-half best index
__device__ double g_loss[NQ];

// ---------------- packed f32x2 helpers (FFMA2 is PTX-only on sm_103a) -----------
__device__ __forceinline__ ull pack2(float a, float b) {
    ull r;
    asm("mov.b64 %0, {%1,%2};" : "=l"(r) : "f"(a), "f"(b));
    return r;
}
__device__ __forceinline__ void fma2(ull& d, ull a, ull b) {
    asm("fma.rn.f32x2 %0, %1, %2, %0;" : "+l"(d) : "l"(a), "l"(b));
}
__device__ __forceinline__ float2 unpack2(ull v) {
    float lo, hi;
    asm("mov.b64 {%0,%1}, %2;" : "=f"(lo), "=f"(hi) : "l"(v));
    return make_float2(lo, hi);
}

// smem (floats): Rs[512][32] + Cs[2 bufs][8][512] + sBV[256] + sBI[256] + RN[32]
// total = 16384 + 8192 + 544 = 25120 floats = 100480 B -> 2 blocks/SM (227 KB)
#define RS_F   16384
#define CS_F   4096                   // one buffer: 8 d x 512 codes
#define SBV_O  (RS_F + 2 * CS_F)      // 24576
#define SBI_O  (SBV_O + 256)
#define RN_O   (SBI_O + 256)
#define SMEM_FLOATS (RN_O + 32)
#define SMEM_BYTES  (SMEM_FLOATS * 4)

// prefetch one [512 codes x 8 d] chunk: 2 x LDG.128 per thread (512 threads)
__device__ __forceinline__ void prefetch2(const float* __restrict__ base, int tid,
                                          float4* pf) {
#pragma unroll
    for (int i = 0; i < 2; i++) {
        const int f  = i * 512 + tid;
        const int k  = f >> 1;       // code 0..511
        const int dg = f & 1;        // d-group (4 d's) 0..1
        pf[i] = *reinterpret_cast<const float4*>(&base[(size_t)k * DIM + dg * 4]);
    }
}

// ---------------- fused GEMM + argmin -------------------------------------------
// One block = 32 tokens x 2048 codes (half codebook). 512 threads = 16 warps:
//   tg = wid&1 : token group (16 tokens), wc = wid>>1 (0..7): 64-code slice of
//   the shared 512-code chunk. Lanes: q = lane&15 -> code-quad, h = lane>>4 ->
//   token half (8 tokens). Per thread: 8 tok x 4 codes = 16 FFMA2/dd.
// TWO blocks co-resident per SM (<=64 regs, ~98 KB smem) -> 8 warps/SMSP to
// hide LDS latency + barrier drain. Best values live in smem [8 wc][32 tok].
// Numerics identical to reference: per (token,code) dot is a sequential-d
// fp32 FMA chain; score = fmaf(-2, dot, rnorm); tie-break lowest index.
__global__ void __launch_bounds__(512, 2)
argmin_kernel(const float* __restrict__ cb)   // codebook for this stage [NCODE][DIM]
{
    extern __shared__ float sm[];
    float* Rs  = sm;                  // [512][32]  Rs[d*32+m]
    float* Cs  = sm + RS_F;           // 2 x [8][512], code-slot swizzled
    float* sBV = sm + SBV_O;          // [8 wc][32 tokens]
    int*   sBI = (int*)(sm + SBI_O);  // [8 wc][32 tokens]
    float* RN  = sm + RN_O;           // [32]

    const int tid  = threadIdx.x;
    const int lane = tid & 31;
    const int wid  = tid >> 5;
    const int tg   = wid & 1;         // token group (16 tokens)
    const int wc   = wid >> 1;        // 64-code slice 0..7 (quads wc*16..+15)
    const int q    = lane & 15;       // code-quad within slice
    const int h    = lane >> 4;       // token half (8 tokens)
    const int n0   = (blockIdx.x >> 1) * 32;
    const int half = blockIdx.x & 1;
    const int k0   = half * (NCODE / 2);

    if (tid < 256) { sBV[tid] = 3.4e38f; sBI[tid] = 0; }
    if (tid < 32)  RN[tid] = g_rnorm[n0 + tid];

    // Fill Rs [32 tokens x 512 d] -> Rs[d][m] (STS bank = m&31 = lane: clean)
#pragma unroll
    for (int it = 0; it < 8; it++) {
        const int f  = it * 512 + tid;
        const int m  = f & 31;
        const int dg = f >> 5;            // 0..127
        const float4 v = *reinterpret_cast<const float4*>(
            &g_residual[(size_t)(n0 + m) * DIM + dg * 4]);
        Rs[(dg * 4 + 0) * 32 + m] = v.x;
        Rs[(dg * 4 + 1) * 32 + m] = v.y;
        Rs[(dg * 4 + 2) * 32 + m] = v.z;
        Rs[(dg * 4 + 3) * 32 + m] = v.w;
    }

    float4 pf[2];
    prefetch2(cb + (size_t)k0 * DIM, tid, pf);
    int buf = 0;
    __syncthreads();                 // Rs, sBV/sBI, RN ready

#pragma unroll 1
    for (int kc = 0; kc < NCODE / 2; kc += 512) {
        ull acc[16];
#pragma unroll
        for (int i = 0; i < 16; i++) acc[i] = 0ull;

#pragma unroll 1
        for (int dk = 0; dk < DIM; dk += 8) {
            float* csw = Cs + buf * CS_F;

            // STS prefetched [512 codes x 8 d] chunk.
            // code k, float j of d-group dg -> word (dg*4+j)*512 + (k ^ (dg<<4))
            // => quad Q of dim dd lives at words dd*512 + 4*(Q ^ ((dd>>2)<<2))
            // banks: (k&31) ^ (dg<<4) distinct across a warp ✓
#pragma unroll
            for (int i = 0; i < 2; i++) {
                const int f  = i * 512 + tid;
                const int k  = f >> 1;
                const int dg = f & 1;
                const int kx = k ^ (dg << 4);
                const float vv[4] = {pf[i].x, pf[i].y, pf[i].z, pf[i].w};
#pragma unroll
                for (int j = 0; j < 4; j++)
                    csw[(dg * 4 + j) * 512 + kx] = vv[j];
            }

            // Prefetch next chunk while computing this one.
            {
                int nkc = kc, ndk = dk + 8;
                if (ndk == DIM) { ndk = 0; nkc = kc + 512; }
                if (nkc < NCODE / 2)
                    prefetch2(cb + (size_t)(k0 + nkc) * DIM + ndk, tid, pf);
            }
            __syncthreads();   // single barrier per chunk (double-buffered Cs)

#pragma unroll
            for (int dd = 0; dd < 8; dd++) {
                const int d = dk + dd;
                // 8 tokens for this lane-half: 4 token pairs via 2 x LDS.128
                const double2* rp = reinterpret_cast<const double2*>(
                    &Rs[d * 32 + tg * 16 + h * 8]);
                const double2 rA = rp[0];          // token pairs (0,1),(2,3)
                const double2 rB = rp[1];          // (4,5),(6,7)
                const ull r01 = __double_as_longlong(rA.x);
                const ull r23 = __double_as_longlong(rA.y);
                const ull r45 = __double_as_longlong(rB.x);
                const ull r67 = __double_as_longlong(rB.y);
                // desired quad Q = wc*16+q stored at slot Q ^ ((dd>>2)<<2)
                const int qx = ((wc * 16 + q) ^ ((dd >> 2) << 2)) & 127;
                const float4 cv = *reinterpret_cast<const float4*>(
                    &csw[dd * 512 + qx * 4]);
                const ull c0 = pack2(cv.x, cv.x);
                const ull c1 = pack2(cv.y, cv.y);
                const ull c2 = pack2(cv.z, cv.z);
                const ull c3 = pack2(cv.w, cv.w);

                fma2(acc[ 0], r01, c0); fma2(acc[ 1], r23, c0);
                fma2(acc[ 2], r45, c0); fma2(acc[ 3], r67, c0);
                fma2(acc[ 4], r01, c1); fma2(acc[ 5], r23, c1);
                fma2(acc[ 6], r45, c1); fma2(acc[ 7], r67, c1);
                fma2(acc[ 8], r01, c2); fma2(acc[ 9], r23, c2);
                fma2(acc[10], r45, c2); fma2(acc[11], r67, c2);
                fma2(acc[12], r01, c3); fma2(acc[13], r23, c3);
                fma2(acc[14], r45, c3); fma2(acc[15], r67, c3);
            }
            buf ^= 1;
        }

        // Epilogue over this 512-code chunk: score = round(rnorm - 2*dot).
        // Code order ascending within thread (t), across lanes (q), across kc;
        // strict '<' + index-aware merges preserve lowest-index tie-break.
#pragma unroll
        for (int p = 0; p < 4; p++) {
            const int nl = tg * 16 + h * 8 + p * 2;     // local token (even)
            const float rn0 = RN[nl];
            const float rn1 = RN[nl + 1];
            float v0 = 3.4e38f, v1 = 3.4e38f;
            int   i0 = 0,       i1 = 0;
#pragma unroll
            for (int t = 0; t < 4; t++) {
                const float2 s = unpack2(acc[t * 4 + p]);
                const int code = k0 + kc + wc * 64 + q * 4 + t;
                const float s0 = fmaf(-2.f, s.x, rn0);
                const float s1 = fmaf(-2.f, s.y, rn1);
                if (s0 < v0) { v0 = s0; i0 = code; }
                if (s1 < v1) { v1 = s1; i1 = code; }
            }
#pragma unroll
            for (int o = 8; o > 0; o >>= 1) {
                float vo = __shfl_down_sync(0xffffffffu, v0, o, 16);
                int   io = __shfl_down_sync(0xffffffffu, i0, o, 16);
                if (vo < v0 || (vo == v0 && io < i0)) { v0 = vo; i0 = io; }
                vo = __shfl_down_sync(0xffffffffu, v1, o, 16);
                io = __shfl_down_sync(0xffffffffu, i1, o, 16);
                if (vo < v1 || (vo == v1 && io < i1)) { v1 = vo; i1 = io; }
            }
            if (q == 0) {   // lanes 0 and 16 write disjoint (wc, token) slots
                const int b = wc * 32 + nl;               // 0..255
                if (v0 < sBV[b] || (v0 == sBV[b] && i0 < sBI[b])) { sBV[b] = v0; sBI[b] = i0; }
                if (v1 < sBV[b+1] || (v1 == sBV[b+1] && i1 < sBI[b+1])) { sBV[b+1] = v1; sBI[b+1] = i1; }
            }
        }
    }

    __syncthreads();
    // Merge the 8 wc slices per token (wc ascending = code ascending).
    if (tid < 32) {
        float v = sBV[tid];
        int   i = sBI[tid];
#pragma unroll
        for (int w = 1; w < 8; w++) {
            const float vw = sBV[w * 32 + tid];
            const int   iw = sBI[w * 32 + tid];
            if (vw < v || (vw == v && iw < i)) { v = vw; i = iw; }
        }
        g_pv[half * N_TOK + n0 + tid] = v;
        g_pi[half * N_TOK + n0 + tid] = i;
    }
}

// ------- per-token: merge halves, residual update, z_q accumulate, loss, rnorm;
// ------- stage 3 fuses the straight-through estimator ----------------------------
__global__ void __launch_bounds__(128)
update_kernel(const float* __restrict__ cb, int stage,
              const float* __restrict__ z,
              float* __restrict__ zq, float* __restrict__ idxf)
{
    const int n = blockIdx.x;
    const int j = threadIdx.x;

    // merge two halves: half 1 wins only if strictly smaller (lower index on ties)
    const float v0 = g_pv[n], v1 = g_pv[N_TOK + n];
    const int k = (v1 < v0) ? g_pi[N_TOK + n] : g_pi[n];
    if (j == 0) idxf[(size_t)n * NQ + stage] = (float)k;

    const size_t off = (size_t)n * DIM + j * 4;
    const float4 r = *reinterpret_cast<float4*>(&g_residual[off]);
    const float4 c = *reinterpret_cast<const float4*>(&cb[(size_t)k * DIM + j * 4]);

    const float4 rn = make_float4(r.x - c.x, r.y - c.y, r.z - c.z, r.w - c.w);
    if (stage < NQ - 1)
        *reinterpret_cast<float4*>(&g_residual[off]) = rn;

    float4 zo;
    if (stage == 0) {
        zo = c;
    } else {
        zo = *reinterpret_cast<float4*>(&zq[off]);
        zo.x += c.x; zo.y += c.y; zo.z += c.z; zo.w += c.w;
    }
    if (stage == NQ - 1) {
        // fused straight-through: z_q = z + (z_q - z), reference fp order
        const float4 zv = *reinterpret_cast<const float4*>(&z[off]);
        zo.x = zv.x + (zo.x - zv.x);
        zo.y = zv.y + (zo.y - zv.y);
        zo.z = zv.z + (zo.z - zv.z);
        zo.w = zv.w + (zo.w - zv.w);
    }
    *reinterpret_cast<float4*>(&zq[off]) = zo;

    // next-stage rnorm + loss on UPDATED residual: (c - r_new)^2
    float rs = fmaf(rn.x, rn.x, fmaf(rn.y, rn.y, fmaf(rn.z, rn.z, rn.w * rn.w)));
    const float4 tt = make_float4(c.x - rn.x, c.y - rn.y, c.z - rn.z, c.w - rn.w);
    float ls = tt.x * tt.x + tt.y * tt.y + tt.z * tt.z + tt.w * tt.w;
#pragma unroll
    for (int o = 16; o > 0; o >>= 1) {
        rs += __shfl_down_sync(0xffffffffu, rs, o);
        ls += __shfl_down_sync(0xffffffffu, ls, o);
    }
    __shared__ float wr[4], wl[4];
    if ((j & 31) == 0) { wr[j >> 5] = rs; wl[j >> 5] = ls; }
    __syncthreads();
    if (j == 0) {
        if (stage < NQ - 1) g_rnorm[n] = (wr[0] + wr[1]) + (wr[2] + wr[3]);
        atomicAdd(&g_loss[stage], (double)((wl[0] + wl[1]) + (wl[2] + wl[3])));
    }
}

// ------- init: residual = z, rnorm(z), loss reset (one block per token) ---------
__global__ void __launch_bounds__(128)
init_kernel(const float* __restrict__ z)
{
    const int n = blockIdx.x;
    const int j = threadIdx.x;
    if (n == 0 && j < NQ) g_loss[j] = 0.0;
    const size_t off = (size_t)n * DIM + j * 4;
    const float4 v = *reinterpret_cast<const float4*>(&z[off]);
    *reinterpret_cast<float4*>(&g_residual[off]) = v;
    float rs = fmaf(v.x, v.x, fmaf(v.y, v.y, fmaf(v.z, v.z, v.w * v.w)));
#pragma unroll
    for (int o = 16; o > 0; o >>= 1) rs += __shfl_down_sync(0xffffffffu, rs, o);
    __shared__ float wr[4];
    if ((j & 31) == 0) wr[j >> 5] = rs;
    __syncthreads();
    if (j == 0) g_rnorm[n] = (wr[0] + wr[1]) + (wr[2] + wr[3]);
}

__global__ void finalize_kernel(float* __restrict__ outloss)
{
    double t = 0.0;
#pragma unroll
    for (int s = 0; s < NQ; s++) t += 1.25 * (g_loss[s] / 16777216.0);
    *outloss = (float)t;
}

// ---------------- launch --------------------------------------------------------
extern "C" void kernel_launch(void* const* d_in, const int* in_sizes, int n_in,
                              void* d_out, int out_size)
{
    const float* z   = (const float*)d_in[0];   // [16,2048,512] f32
    const float* cbs = (const float*)d_in[1];   // [4,4096,512]  f32
    float* out   = (float*)d_out;
    float* zq    = out;                                       // 16,777,216
    float* idxf  = out + (size_t)N_TOK * DIM;                 // 131,072
    float* lossp = idxf + (size_t)N_TOK * NQ;                 // 1

    cudaFuncSetAttribute(argmin_kernel,
                         cudaFuncAttributeMaxDynamicSharedMemorySize, SMEM_BYTES);

    init_kernel<<<N_TOK, 128>>>(z);

    for (int s = 0; s < NQ; s++) {
        const float* cb_s = cbs + (size_t)s * NCODE * DIM;
        argmin_kernel<<<(N_TOK / 32) * 2, 512, SMEM_BYTES>>>(cb_s);
        update_kernel<<<N_TOK, 128>>>(cb_s, s, z, zq, idxf);
    }
    finalize_kernel<<<1, 1>>>(lossp);
}